// round 3
// baseline (speedup 1.0000x reference)
#include <cuda_runtime.h>
#include <cuda_fp16.h>
#include <stdint.h>

// Problem dims
#define BATCH 64
#define SEQ   512
#define DIN   256
#define HID   1024
#define NG    4096            // 4*HID
#define MTOT  32768           // BATCH*SEQ

// ---------------- scratch (device globals; no allocations allowed) ------------
__device__ __half g_X2[(size_t)MTOT * DIN];          // 16.8 MB  X in fp16
__device__ __half g_WxT[(size_t)NG * DIN];           //  2 MB    Wx^T  [n][k]
__device__ __half g_WhT[(size_t)NG * HID];           //  8.4 MB  Wh^T  [n][k]
__device__ float  g_bias[NG];
__device__ float  g_xg[(size_t)MTOT * NG];           // 537 MB   X@Wx+b
__device__ __half g_H2[2][BATCH * HID];              // ping-pong H (fp16)
__device__ float  g_C[BATCH * HID];                  // cell state (fp32)
__device__ float  g_Hs[(size_t)MTOT * HID];          // 134 MB   all H_t (fp32)

// ---------------- helpers -----------------------------------------------------
__device__ __forceinline__ void mma16816(float c[4],
    uint32_t a0, uint32_t a1, uint32_t a2, uint32_t a3,
    uint32_t b0, uint32_t b1)
{
    asm volatile(
        "mma.sync.aligned.m16n8k16.row.col.f32.f16.f16.f32 "
        "{%0,%1,%2,%3}, {%4,%5,%6,%7}, {%8,%9}, {%0,%1,%2,%3};\n"
        : "+f"(c[0]), "+f"(c[1]), "+f"(c[2]), "+f"(c[3])
        : "r"(a0), "r"(a1), "r"(a2), "r"(a3), "r"(b0), "r"(b1));
}

__device__ __forceinline__ float sigf(float x) { return 1.0f / (1.0f + __expf(-x)); }

// ---------------- prep kernels ------------------------------------------------
__global__ void k_convX(const float* __restrict__ X)
{
    size_t i = (size_t)blockIdx.x * blockDim.x + threadIdx.x;
    if (i < (size_t)MTOT * DIN) g_X2[i] = __float2half(X[i]);
}

__global__ void k_prepWxT(const float* __restrict__ Wxi, const float* __restrict__ Wxf,
                          const float* __restrict__ Wxo, const float* __restrict__ Wxc)
{
    int idx = blockIdx.x * blockDim.x + threadIdx.x;       // over NG*DIN
    if (idx >= NG * DIN) return;
    int n = idx >> 8;          // /256
    int k = idx & 255;
    int gate = n >> 10, h = n & 1023;
    const float* W = (gate == 0) ? Wxi : (gate == 1) ? Wxf : (gate == 2) ? Wxo : Wxc;
    g_WxT[idx] = __float2half(W[k * HID + h]);
}

__global__ void k_prepWhT(const float* __restrict__ Whi, const float* __restrict__ Whf,
                          const float* __restrict__ Who, const float* __restrict__ Whc)
{
    int idx = blockIdx.x * blockDim.x + threadIdx.x;       // over NG*HID
    if (idx >= NG * HID) return;
    int n = idx >> 10;         // /1024
    int k = idx & 1023;
    int gate = n >> 10, h = n & 1023;
    const float* W = (gate == 0) ? Whi : (gate == 1) ? Whf : (gate == 2) ? Who : Whc;
    g_WhT[idx] = __float2half(W[k * HID + h]);
}

__global__ void k_prepBias(const float* __restrict__ bi, const float* __restrict__ bf,
                           const float* __restrict__ bo, const float* __restrict__ bc)
{
    int n = blockIdx.x * blockDim.x + threadIdx.x;
    if (n >= NG) return;
    int gate = n >> 10, h = n & 1023;
    const float* b = (gate == 0) ? bi : (gate == 1) ? bf : (gate == 2) ? bo : bc;
    g_bias[n] = b[h];
}

__global__ void k_prepState(const float* __restrict__ H0, const float* __restrict__ C0)
{
    int i = blockIdx.x * blockDim.x + threadIdx.x;
    if (i >= BATCH * HID) return;
    g_H2[0][i] = __float2half(H0[i]);
    g_C[i] = C0[i];
}

// ---------------- phase 1: xg = X @ Wx + b  (fp16 MMA, fp32 acc) --------------
// grid: (NG/32, MTOT/64), block: 128 (4 warps, each warp = 16 M-rows x 32 N-cols)
__global__ void __launch_bounds__(128) k_xg()
{
    const int warp = threadIdx.x >> 5;
    const int lane = threadIdx.x & 31;
    const int gid  = lane >> 2;
    const int tig  = lane & 3;
    const int m0   = blockIdx.y * 64 + warp * 16 + gid;
    const int m1   = m0 + 8;
    const int n_base = blockIdx.x * 32;

    float c[4][4];
#pragma unroll
    for (int nc = 0; nc < 4; nc++)
#pragma unroll
        for (int r = 0; r < 4; r++) c[nc][r] = 0.0f;

#pragma unroll 4
    for (int k0 = 0; k0 < DIN; k0 += 16) {
        int ka = k0 + tig * 2;
        uint32_t a0 = *(const uint32_t*)&g_X2[(size_t)m0 * DIN + ka];
        uint32_t a1 = *(const uint32_t*)&g_X2[(size_t)m1 * DIN + ka];
        uint32_t a2 = *(const uint32_t*)&g_X2[(size_t)m0 * DIN + ka + 8];
        uint32_t a3 = *(const uint32_t*)&g_X2[(size_t)m1 * DIN + ka + 8];
#pragma unroll
        for (int nc = 0; nc < 4; nc++) {
            int n = n_base + nc * 8 + gid;
            uint32_t b0 = *(const uint32_t*)&g_WxT[(size_t)n * DIN + ka];
            uint32_t b1 = *(const uint32_t*)&g_WxT[(size_t)n * DIN + ka + 8];
            mma16816(c[nc], a0, a1, a2, a3, b0, b1);
        }
    }

#pragma unroll
    for (int nc = 0; nc < 4; nc++) {
        int col = n_base + nc * 8 + tig * 2;
        float bx = g_bias[col], by = g_bias[col + 1];
        float2 v0 = make_float2(c[nc][0] + bx, c[nc][1] + by);
        float2 v1 = make_float2(c[nc][2] + bx, c[nc][3] + by);
        *(float2*)&g_xg[(size_t)m0 * NG + col] = v0;
        *(float2*)&g_xg[(size_t)m1 * NG + col] = v1;
    }
}

// ---------------- scan step: g = xg_t + H @ Wh ; gates ; update C,H -----------
// grid: 128 blocks (h-tile of 8), block: 128 (4 warps = 4 x 16 batch rows)
__global__ void __launch_bounds__(128) k_step(int t, int par)
{
    const int warp = threadIdx.x >> 5;
    const int lane = threadIdx.x & 31;
    const int gid  = lane >> 2;
    const int tig  = lane & 3;
    const int b0r  = warp * 16 + gid;        // batch row
    const int b1r  = b0r + 8;
    const int h0   = blockIdx.x * 8;
    const __half* __restrict__ Hin = g_H2[par];
    __half* __restrict__ Hout = g_H2[par ^ 1];

    const int m0 = b0r * SEQ + t;
    const int m1 = b1r * SEQ + t;

    float c[4][4];
#pragma unroll
    for (int g = 0; g < 4; g++) {
        int col = g * HID + h0 + tig * 2;
        float2 x0 = *(const float2*)&g_xg[(size_t)m0 * NG + col];
        float2 x1 = *(const float2*)&g_xg[(size_t)m1 * NG + col];
        c[g][0] = x0.x; c[g][1] = x0.y; c[g][2] = x1.x; c[g][3] = x1.y;
    }

#pragma unroll 4
    for (int k0 = 0; k0 < HID; k0 += 16) {
        int ka = k0 + tig * 2;
        uint32_t a0 = *(const uint32_t*)&Hin[(size_t)b0r * HID + ka];
        uint32_t a1 = *(const uint32_t*)&Hin[(size_t)b1r * HID + ka];
        uint32_t a2 = *(const uint32_t*)&Hin[(size_t)b0r * HID + ka + 8];
        uint32_t a3 = *(const uint32_t*)&Hin[(size_t)b1r * HID + ka + 8];
#pragma unroll
        for (int g = 0; g < 4; g++) {
            int n = g * HID + h0 + gid;
            uint32_t b0 = *(const uint32_t*)&g_WhT[(size_t)n * HID + ka];
            uint32_t b1 = *(const uint32_t*)&g_WhT[(size_t)n * HID + ka + 8];
            mma16816(c[g], a0, a1, a2, a3, b0, b1);
        }
    }

    // epilogue: gates + state update. regs {0,1}=row b0r, {2,3}=row b1r; cols h0+tig*2+{0,1}
#pragma unroll
    for (int p = 0; p < 2; p++) {
        int b  = p ? b1r : b0r;
        int ri = p * 2;
#pragma unroll
        for (int q = 0; q < 2; q++) {
            int h = h0 + tig * 2 + q;
            float gi = c[0][ri + q];
            float gf = c[1][ri + q];
            float go = c[2][ri + q];
            float gc = c[3][ri + q];
            float iv = sigf(gi), fv = sigf(gf), ov = sigf(go), cv = tanhf(gc);
            int idx = b * HID + h;
            float Cn = fv * g_C[idx] + iv * cv;
            g_C[idx] = Cn;
            float Hn = ov * tanhf(Cn);
            Hout[idx] = __float2half(Hn);
            g_Hs[(size_t)(b * SEQ + t) * HID + h] = Hn;
        }
    }
}

// ---------------- pred = Hs @ Wd + bd ----------------------------------------
__global__ void k_pred(const float* __restrict__ Wd, const float* __restrict__ bd,
                       float* __restrict__ out, int out_size)
{
    int wg   = (blockIdx.x * blockDim.x + threadIdx.x) >> 5;   // one warp per row
    int lane = threadIdx.x & 31;
    if (wg >= MTOT) return;
    float s = 0.0f;
    const float* row = &g_Hs[(size_t)wg * HID];
#pragma unroll 8
    for (int k = lane; k < HID; k += 32) s += row[k] * Wd[k];
#pragma unroll
    for (int off = 16; off; off >>= 1) s += __shfl_down_sync(0xFFFFFFFFu, s, off);
    if (lane == 0 && wg < out_size) out[wg] = s + bd[0];
}

// ---------------- final Hf / Cf copy-out -------------------------------------
__global__ void k_final(float* __restrict__ out, int out_size)
{
    int i = blockIdx.x * blockDim.x + threadIdx.x;
    if (i >= BATCH * HID) return;
    int b = i >> 10, h = i & 1023;
    int o1 = MTOT + i;                  // Hf
    int o2 = MTOT + BATCH * HID + i;    // Cf
    if (o1 < out_size) out[o1] = g_Hs[(size_t)(b * SEQ + (SEQ - 1)) * HID + h];
    if (o2 < out_size) out[o2] = g_C[i];
}

// ---------------- launch ------------------------------------------------------
extern "C" void kernel_launch(void* const* d_in, const int* in_sizes, int n_in,
                              void* d_out, int out_size)
{
    const float* X   = (const float*)d_in[0];
    const float* H0  = (const float*)d_in[1];
    const float* C0  = (const float*)d_in[2];
    const float* Wxi = (const float*)d_in[3];
    const float* Whi = (const float*)d_in[4];
    const float* bi  = (const float*)d_in[5];
    const float* Wxf = (const float*)d_in[6];
    const float* Whf = (const float*)d_in[7];
    const float* bf  = (const float*)d_in[8];
    const float* Wxo = (const float*)d_in[9];
    const float* Who = (const float*)d_in[10];
    const float* bo  = (const float*)d_in[11];
    const float* Wxc = (const float*)d_in[12];
    const float* Whc = (const float*)d_in[13];
    const float* bc  = (const float*)d_in[14];
    const float* Wd  = (const float*)d_in[15];
    const float* bd  = (const float*)d_in[16];
    float* out = (float*)d_out;

    // prep
    k_convX<<<(MTOT * DIN + 1023) / 1024, 1024>>>(X);
    k_prepWxT<<<(NG * DIN + 255) / 256, 256>>>(Wxi, Wxf, Wxo, Wxc);
    k_prepWhT<<<(NG * HID + 255) / 256, 256>>>(Whi, Whf, Who, Whc);
    k_prepBias<<<(NG + 255) / 256, 256>>>(bi, bf, bo, bc);
    k_prepState<<<(BATCH * HID + 255) / 256, 256>>>(H0, C0);

    // phase 1: xg
    dim3 g1(NG / 32, MTOT / 64);
    k_xg<<<g1, 128>>>();

    // sequential scan
    for (int t = 0; t < SEQ; t++) {
        k_step<<<128, 128>>>(t, t & 1);
    }

    // outputs
    k_pred<<<(MTOT * 32 + 255) / 256, 256>>>(Wd, bd, out, out_size);
    k_final<<<(BATCH * HID + 255) / 256, 256>>>(out, out_size);
}

// round 4
// speedup vs baseline: 1.6278x; 1.6278x over previous
#include <cuda_runtime.h>
#include <cuda_fp16.h>
#include <stdint.h>

// Problem dims
#define BATCH 64
#define SEQ   512
#define DIN   256
#define HID   1024
#define NG    4096            // 4*HID
#define MTOT  32768           // BATCH*SEQ

// ---------------- scratch (device globals; no allocations allowed) ------------
__device__ __half g_X2[(size_t)MTOT * DIN];          // 16.8 MB  X in fp16
__device__ __half g_WxT[(size_t)NG * DIN];           //  2 MB    Wx^T  [n][k]
__device__ __half g_WhT[(size_t)NG * HID];           //  8.4 MB  Wh^T  [n][k]
__device__ float  g_bias[NG];
__device__ float  g_xg[(size_t)MTOT * NG];           // 537 MB   xg, layout [t][b][4H]
__device__ __half g_H2[2][BATCH * HID];              // ping-pong H (fp16)
__device__ float  g_C[BATCH * HID];                  // cell state (fp32)
__device__ float  g_Hs[(size_t)MTOT * HID];          // 134 MB   all H_t (fp32), [b*SEQ+t][h]
__device__ unsigned g_bar_count;                     // grid barrier counter

// ---------------- helpers -----------------------------------------------------
__device__ __forceinline__ void mma16816(float c[4],
    uint32_t a0, uint32_t a1, uint32_t a2, uint32_t a3,
    uint32_t b0, uint32_t b1)
{
    asm volatile(
        "mma.sync.aligned.m16n8k16.row.col.f32.f16.f16.f32 "
        "{%0,%1,%2,%3}, {%4,%5,%6,%7}, {%8,%9}, {%0,%1,%2,%3};\n"
        : "+f"(c[0]), "+f"(c[1]), "+f"(c[2]), "+f"(c[3])
        : "r"(a0), "r"(a1), "r"(a2), "r"(a3), "r"(b0), "r"(b1));
}

__device__ __forceinline__ float sigf(float x) { return 1.0f / (1.0f + __expf(-x)); }

__device__ __forceinline__ uint32_t ldcg_u32(const __half* p) {
    uint32_t v;
    asm volatile("ld.global.cg.b32 %0, [%1];" : "=r"(v) : "l"(p));
    return v;
}
__device__ __forceinline__ float2 ldcg_f2(const float* p) {
    float2 v;
    asm volatile("ld.global.cg.v2.f32 {%0,%1}, [%2];" : "=f"(v.x), "=f"(v.y) : "l"(p));
    return v;
}

// ---------------- prep kernels ------------------------------------------------
__global__ void k_init()
{
    if (threadIdx.x == 0 && blockIdx.x == 0) g_bar_count = 0u;
}

__global__ void k_convX(const float* __restrict__ X)
{
    size_t i = (size_t)blockIdx.x * blockDim.x + threadIdx.x;
    if (i < (size_t)MTOT * DIN) g_X2[i] = __float2half(X[i]);
}

__global__ void k_prepWxT(const float* __restrict__ Wxi, const float* __restrict__ Wxf,
                          const float* __restrict__ Wxo, const float* __restrict__ Wxc)
{
    int idx = blockIdx.x * blockDim.x + threadIdx.x;       // over NG*DIN
    if (idx >= NG * DIN) return;
    int n = idx >> 8;          // /256
    int k = idx & 255;
    int gate = n >> 10, h = n & 1023;
    const float* W = (gate == 0) ? Wxi : (gate == 1) ? Wxf : (gate == 2) ? Wxo : Wxc;
    g_WxT[idx] = __float2half(W[k * HID + h]);
}

__global__ void k_prepWhT(const float* __restrict__ Whi, const float* __restrict__ Whf,
                          const float* __restrict__ Who, const float* __restrict__ Whc)
{
    int idx = blockIdx.x * blockDim.x + threadIdx.x;       // over NG*HID
    if (idx >= NG * HID) return;
    int n = idx >> 10;         // /1024
    int k = idx & 1023;
    int gate = n >> 10, h = n & 1023;
    const float* W = (gate == 0) ? Whi : (gate == 1) ? Whf : (gate == 2) ? Who : Whc;
    g_WhT[idx] = __float2half(W[k * HID + h]);
}

__global__ void k_prepBias(const float* __restrict__ bi, const float* __restrict__ bf,
                           const float* __restrict__ bo, const float* __restrict__ bc)
{
    int n = blockIdx.x * blockDim.x + threadIdx.x;
    if (n >= NG) return;
    int gate = n >> 10, h = n & 1023;
    const float* b = (gate == 0) ? bi : (gate == 1) ? bf : (gate == 2) ? bo : bc;
    g_bias[n] = b[h];
}

__global__ void k_prepState(const float* __restrict__ H0, const float* __restrict__ C0)
{
    int i = blockIdx.x * blockDim.x + threadIdx.x;
    if (i >= BATCH * HID) return;
    g_H2[0][i] = __float2half(H0[i]);
    g_C[i] = C0[i];
}

// ---------------- phase 1: xg = X @ Wx + b  (fp16 MMA, fp32 acc) --------------
// grid: (NG/32, MTOT/64), block: 128 (4 warps, each warp = 16 M-rows x 32 N-cols)
// Output layout: g_xg[(s*64 + b)*NG + col]
__global__ void __launch_bounds__(128) k_xg()
{
    const int warp = threadIdx.x >> 5;
    const int lane = threadIdx.x & 31;
    const int gid  = lane >> 2;
    const int tig  = lane & 3;
    const int m0   = blockIdx.y * 64 + warp * 16 + gid;
    const int m1   = m0 + 8;
    const int n_base = blockIdx.x * 32;

    float c[4][4];
#pragma unroll
    for (int nc = 0; nc < 4; nc++)
#pragma unroll
        for (int r = 0; r < 4; r++) c[nc][r] = 0.0f;

#pragma unroll 4
    for (int k0 = 0; k0 < DIN; k0 += 16) {
        int ka = k0 + tig * 2;
        uint32_t a0 = *(const uint32_t*)&g_X2[(size_t)m0 * DIN + ka];
        uint32_t a1 = *(const uint32_t*)&g_X2[(size_t)m1 * DIN + ka];
        uint32_t a2 = *(const uint32_t*)&g_X2[(size_t)m0 * DIN + ka + 8];
        uint32_t a3 = *(const uint32_t*)&g_X2[(size_t)m1 * DIN + ka + 8];
#pragma unroll
        for (int nc = 0; nc < 4; nc++) {
            int n = n_base + nc * 8 + gid;
            uint32_t b0 = *(const uint32_t*)&g_WxT[(size_t)n * DIN + ka];
            uint32_t b1 = *(const uint32_t*)&g_WxT[(size_t)n * DIN + ka + 8];
            mma16816(c[nc], a0, a1, a2, a3, b0, b1);
        }
    }

    // store to [t][b][col] layout
    const int b0i = m0 >> 9, s0 = m0 & 511;
    const int b1i = m1 >> 9, s1 = m1 & 511;
    const size_t row0 = (size_t)s0 * BATCH + b0i;
    const size_t row1 = (size_t)s1 * BATCH + b1i;
#pragma unroll
    for (int nc = 0; nc < 4; nc++) {
        int col = n_base + nc * 8 + tig * 2;
        float bx = g_bias[col], by = g_bias[col + 1];
        float2 v0 = make_float2(c[nc][0] + bx, c[nc][1] + by);
        float2 v1 = make_float2(c[nc][2] + bx, c[nc][3] + by);
        *(float2*)&g_xg[row0 * NG + col] = v0;
        *(float2*)&g_xg[row1 * NG + col] = v1;
    }
}

// ---------------- persistent scan kernel --------------------------------------
// grid: 128 blocks x 128 threads. Block owns h-slice [h0, h0+8) across 4 gates.
// Wh slice (32 n-rows x 1024 k) cached in smem for the whole scan.
// C state lives in registers. Grid-wide barrier between steps.
#define SW_STRIDE 1032   // padded row stride in halfs (conflict-free LDS)

__global__ void __launch_bounds__(128, 1) k_scan()
{
    extern __shared__ __half sWh[];   // [32][SW_STRIDE]

    const int tid  = threadIdx.x;
    const int warp = tid >> 5;
    const int lane = tid & 31;
    const int gid  = lane >> 2;
    const int tig  = lane & 3;
    const int h0   = blockIdx.x * 8;
    const int r0   = warp * 16 + gid;    // batch row A
    const int r1   = r0 + 8;             // batch row B

    // ---- load Wh slice into smem (once) ----
    // 32 n-rows (g*8+hh) x 1024 halfs; vectorized uint4 (8 halfs)
    for (int i = tid; i < 32 * 128; i += 128) {
        int row = i >> 7;             // 0..31
        int c8  = (i & 127) * 8;      // half offset
        int g   = row >> 3, hh = row & 7;
        uint4 v = *(const uint4*)&g_WhT[((size_t)(g * HID + h0 + hh)) * HID + c8];
        *(uint4*)&sWh[row * SW_STRIDE + c8] = v;
    }
    __syncthreads();

    // ---- C state in registers ----
    const int hc = h0 + tig * 2;
    float C00 = g_C[r0 * HID + hc];
    float C01 = g_C[r0 * HID + hc + 1];
    float C10 = g_C[r1 * HID + hc];
    float C11 = g_C[r1 * HID + hc + 1];

    for (int t = 0; t < SEQ; t++) {
        const __half* __restrict__ Hin  = g_H2[t & 1];
        __half* __restrict__       Hout = g_H2[(t + 1) & 1];

        // accumulators init = xg_t
        float c[4][4];
        const size_t xr0 = ((size_t)t * BATCH + r0) * NG;
        const size_t xr1 = ((size_t)t * BATCH + r1) * NG;
#pragma unroll
        for (int g = 0; g < 4; g++) {
            int col = g * HID + hc;
            float2 x0 = ldcg_f2(&g_xg[xr0 + col]);
            float2 x1 = ldcg_f2(&g_xg[xr1 + col]);
            c[g][0] = x0.x; c[g][1] = x0.y; c[g][2] = x1.x; c[g][3] = x1.y;
        }

        // K loop: g += H @ Wh
#pragma unroll 4
        for (int k0 = 0; k0 < HID; k0 += 16) {
            int ka = k0 + tig * 2;
            uint32_t a0 = ldcg_u32(&Hin[r0 * HID + ka]);
            uint32_t a1 = ldcg_u32(&Hin[r1 * HID + ka]);
            uint32_t a2 = ldcg_u32(&Hin[r0 * HID + ka + 8]);
            uint32_t a3 = ldcg_u32(&Hin[r1 * HID + ka + 8]);
#pragma unroll
            for (int g = 0; g < 4; g++) {
                const __half* brow = &sWh[(g * 8 + gid) * SW_STRIDE + ka];
                uint32_t b0 = *(const uint32_t*)brow;
                uint32_t b1 = *(const uint32_t*)(brow + 8);
                mma16816(c[g], a0, a1, a2, a3, b0, b1);
            }
        }

        // epilogue: gates, C/H update
#pragma unroll
        for (int p = 0; p < 2; p++) {
            int br = p ? r1 : r0;
            int ri = p * 2;
            float iv0 = sigf(c[0][ri]),     iv1 = sigf(c[0][ri + 1]);
            float fv0 = sigf(c[1][ri]),     fv1 = sigf(c[1][ri + 1]);
            float ov0 = sigf(c[2][ri]),     ov1 = sigf(c[2][ri + 1]);
            float cv0 = tanhf(c[3][ri]),    cv1 = tanhf(c[3][ri + 1]);
            float Ca = p ? C10 : C00;
            float Cb = p ? C11 : C01;
            float Cn0 = fv0 * Ca + iv0 * cv0;
            float Cn1 = fv1 * Cb + iv1 * cv1;
            if (p) { C10 = Cn0; C11 = Cn1; } else { C00 = Cn0; C01 = Cn1; }
            float Hn0 = ov0 * tanhf(Cn0);
            float Hn1 = ov1 * tanhf(Cn1);
            // fp16 H for next step
            __half2 hv = __floats2half2_rn(Hn0, Hn1);
            asm volatile("st.global.cg.b32 [%0], %1;" ::
                         "l"(&Hout[br * HID + hc]), "r"(*(uint32_t*)&hv));
            // fp32 record for outputs
            float2 hf = make_float2(Hn0, Hn1);
            asm volatile("st.global.cg.v2.f32 [%0], {%1,%2};" ::
                         "l"(&g_Hs[((size_t)br * SEQ + t) * HID + hc]), "f"(hf.x), "f"(hf.y));
        }

        // ---- grid-wide barrier ----
        __threadfence();
        __syncthreads();
        if (tid == 0) {
            atomicAdd(&g_bar_count, 1u);
            unsigned target = 128u * (unsigned)(t + 1);
            volatile unsigned* p = &g_bar_count;
            while (*p < target) { __nanosleep(40); }
            __threadfence();
        }
        __syncthreads();
    }

    // write back C state
    g_C[r0 * HID + hc]     = C00;
    g_C[r0 * HID + hc + 1] = C01;
    g_C[r1 * HID + hc]     = C10;
    g_C[r1 * HID + hc + 1] = C11;
}

// ---------------- pred = Hs @ Wd + bd ----------------------------------------
__global__ void k_pred(const float* __restrict__ Wd, const float* __restrict__ bd,
                       float* __restrict__ out, int out_size)
{
    int wg   = (blockIdx.x * blockDim.x + threadIdx.x) >> 5;   // one warp per row
    int lane = threadIdx.x & 31;
    if (wg >= MTOT) return;
    float s = 0.0f;
    const float* row = &g_Hs[(size_t)wg * HID];
#pragma unroll 8
    for (int k = lane; k < HID; k += 32) s += row[k] * Wd[k];
#pragma unroll
    for (int off = 16; off; off >>= 1) s += __shfl_down_sync(0xFFFFFFFFu, s, off);
    if (lane == 0 && wg < out_size) out[wg] = s + bd[0];
}

// ---------------- final Hf / Cf copy-out -------------------------------------
__global__ void k_final(float* __restrict__ out, int out_size)
{
    int i = blockIdx.x * blockDim.x + threadIdx.x;
    if (i >= BATCH * HID) return;
    int b = i >> 10, h = i & 1023;
    int o1 = MTOT + i;                  // Hf
    int o2 = MTOT + BATCH * HID + i;    // Cf
    if (o1 < out_size) out[o1] = g_Hs[(size_t)(b * SEQ + (SEQ - 1)) * HID + h];
    if (o2 < out_size) out[o2] = g_C[i];
}

// ---------------- launch ------------------------------------------------------
extern "C" void kernel_launch(void* const* d_in, const int* in_sizes, int n_in,
                              void* d_out, int out_size)
{
    const float* X   = (const float*)d_in[0];
    const float* H0  = (const float*)d_in[1];
    const float* C0  = (const float*)d_in[2];
    const float* Wxi = (const float*)d_in[3];
    const float* Whi = (const float*)d_in[4];
    const float* bi  = (const float*)d_in[5];
    const float* Wxf = (const float*)d_in[6];
    const float* Whf = (const float*)d_in[7];
    const float* bf  = (const float*)d_in[8];
    const float* Wxo = (const float*)d_in[9];
    const float* Who = (const float*)d_in[10];
    const float* bo  = (const float*)d_in[11];
    const float* Wxc = (const float*)d_in[12];
    const float* Whc = (const float*)d_in[13];
    const float* bc  = (const float*)d_in[14];
    const float* Wd  = (const float*)d_in[15];
    const float* bd  = (const float*)d_in[16];
    float* out = (float*)d_out;

    // persistent scan smem: 32 * 1032 * 2 bytes = 66048; pad to 160KB to force
    // 1 block/SM so all 128 blocks are co-resident (barrier safety).
    static int smem_set = 0;
    const int SCAN_SMEM = 160 * 1024;
    if (!smem_set) {
        cudaFuncSetAttribute(k_scan, cudaFuncAttributeMaxDynamicSharedMemorySize, SCAN_SMEM);
        smem_set = 1;
    }

    // prep
    k_init<<<1, 32>>>();
    k_convX<<<(MTOT * DIN + 1023) / 1024, 1024>>>(X);
    k_prepWxT<<<(NG * DIN + 255) / 256, 256>>>(Wxi, Wxf, Wxo, Wxc);
    k_prepWhT<<<(NG * HID + 255) / 256, 256>>>(Whi, Whf, Who, Whc);
    k_prepBias<<<(NG + 255) / 256, 256>>>(bi, bf, bo, bc);
    k_prepState<<<(BATCH * HID + 255) / 256, 256>>>(H0, C0);

    // phase 1: xg
    dim3 g1(NG / 32, MTOT / 64);
    k_xg<<<g1, 128>>>();

    // persistent scan (all 512 steps in one kernel)
    k_scan<<<128, 128, SCAN_SMEM>>>();

    // outputs
    k_pred<<<(MTOT * 32 + 255) / 256, 256>>>(Wd, bd, out, out_size);
    k_final<<<(BATCH * HID + 255) / 256, 256>>>(out, out_size);
}

// round 6
// speedup vs baseline: 2.5532x; 1.5685x over previous
#include <cuda_runtime.h>
#include <cuda_fp16.h>
#include <stdint.h>

// Problem dims
#define BATCH 64
#define SEQ   512
#define DIN   256
#define HID   1024
#define NG    4096            // 4*HID
#define MTOT  32768           // BATCH*SEQ

// ---------------- scratch (device globals; no allocations allowed) ------------
__device__ __half g_X2[(size_t)MTOT * DIN];          // 16.8 MB  X in fp16
__device__ __half g_WxT[(size_t)NG * DIN];           //  2 MB    Wx^T  [n][k]
__device__ __half g_WhT[(size_t)NG * HID];           //  8.4 MB  Wh^T  [n][k]
__device__ float  g_bias[NG];
__device__ float  g_xg[(size_t)MTOT * NG];           // 537 MB   xg, layout [t][b][4H]
__device__ __half g_H2[2][BATCH * HID];              // ping-pong H (fp16)
__device__ float  g_C[BATCH * HID];                  // cell state (fp32)
__device__ float  g_Hs[(size_t)MTOT * HID];          // 134 MB   all H_t (fp32), [b*SEQ+t][h]
__device__ unsigned g_bar_count;                     // grid barrier counter

// ---------------- helpers -----------------------------------------------------
__device__ __forceinline__ void mma16816(float c[4],
    uint32_t a0, uint32_t a1, uint32_t a2, uint32_t a3,
    uint32_t b0, uint32_t b1)
{
    asm volatile(
        "mma.sync.aligned.m16n8k16.row.col.f32.f16.f16.f32 "
        "{%0,%1,%2,%3}, {%4,%5,%6,%7}, {%8,%9}, {%0,%1,%2,%3};\n"
        : "+f"(c[0]), "+f"(c[1]), "+f"(c[2]), "+f"(c[3])
        : "r"(a0), "r"(a1), "r"(a2), "r"(a3), "r"(b0), "r"(b1));
}

__device__ __forceinline__ float sigf(float x) { return 1.0f / (1.0f + __expf(-x)); }

__device__ __forceinline__ float2 ldcg_f2(const float* p) {
    float2 v;
    asm volatile("ld.global.cg.v2.f32 {%0,%1}, [%2];" : "=f"(v.x), "=f"(v.y) : "l"(p));
    return v;
}

__device__ __forceinline__ uint32_t smem_u32(const void* p) {
    uint32_t a;
    asm("{ .reg .u64 t; cvta.to.shared.u64 t, %1; cvt.u32.u64 %0, t; }" : "=r"(a) : "l"(p));
    return a;
}

__device__ __forceinline__ void cp_async16(uint32_t dst, const void* src) {
    asm volatile("cp.async.cg.shared.global [%0], [%1], 16;" :: "r"(dst), "l"(src));
}

// ---------------- prep kernels ------------------------------------------------
__global__ void k_init()
{
    if (threadIdx.x == 0 && blockIdx.x == 0) g_bar_count = 0u;
}

__global__ void k_convX(const float* __restrict__ X)
{
    size_t i = (size_t)blockIdx.x * blockDim.x + threadIdx.x;
    if (i < (size_t)MTOT * DIN) g_X2[i] = __float2half(X[i]);
}

__global__ void k_prepWxT(const float* __restrict__ Wxi, const float* __restrict__ Wxf,
                          const float* __restrict__ Wxo, const float* __restrict__ Wxc)
{
    int idx = blockIdx.x * blockDim.x + threadIdx.x;       // over NG*DIN
    if (idx >= NG * DIN) return;
    int n = idx >> 8;          // /256
    int k = idx & 255;
    int gate = n >> 10, h = n & 1023;
    const float* W = (gate == 0) ? Wxi : (gate == 1) ? Wxf : (gate == 2) ? Wxo : Wxc;
    g_WxT[idx] = __float2half(W[k * HID + h]);
}

__global__ void k_prepWhT(const float* __restrict__ Whi, const float* __restrict__ Whf,
                          const float* __restrict__ Who, const float* __restrict__ Whc)
{
    int idx = blockIdx.x * blockDim.x + threadIdx.x;       // over NG*HID
    if (idx >= NG * HID) return;
    int n = idx >> 10;         // /1024
    int k = idx & 1023;
    int gate = n >> 10, h = n & 1023;
    const float* W = (gate == 0) ? Whi : (gate == 1) ? Whf : (gate == 2) ? Who : Whc;
    g_WhT[idx] = __float2half(W[k * HID + h]);
}

__global__ void k_prepBias(const float* __restrict__ bi, const float* __restrict__ bf,
                           const float* __restrict__ bo, const float* __restrict__ bc)
{
    int n = blockIdx.x * blockDim.x + threadIdx.x;
    if (n >= NG) return;
    int gate = n >> 10, h = n & 1023;
    const float* b = (gate == 0) ? bi : (gate == 1) ? bf : (gate == 2) ? bo : bc;
    g_bias[n] = b[h];
}

__global__ void k_prepState(const float* __restrict__ H0, const float* __restrict__ C0)
{
    int i = blockIdx.x * blockDim.x + threadIdx.x;
    if (i >= BATCH * HID) return;
    g_H2[0][i] = __float2half(H0[i]);
    g_C[i] = C0[i];
}

// ---------------- phase 1: xg = X @ Wx + b  (fp16 MMA, fp32 acc) --------------
// grid: (NG/32, MTOT/64), block: 128 (4 warps, each warp = 16 M-rows x 32 N-cols)
// Output layout: g_xg[(s*64 + b)*NG + col]
__global__ void __launch_bounds__(128) k_xg()
{
    const int warp = threadIdx.x >> 5;
    const int lane = threadIdx.x & 31;
    const int gid  = lane >> 2;
    const int tig  = lane & 3;
    const int m0   = blockIdx.y * 64 + warp * 16 + gid;
    const int m1   = m0 + 8;
    const int n_base = blockIdx.x * 32;

    float c[4][4];
#pragma unroll
    for (int nc = 0; nc < 4; nc++)
#pragma unroll
        for (int r = 0; r < 4; r++) c[nc][r] = 0.0f;

#pragma unroll 4
    for (int k0 = 0; k0 < DIN; k0 += 16) {
        int ka = k0 + tig * 2;
        uint32_t a0 = *(const uint32_t*)&g_X2[(size_t)m0 * DIN + ka];
        uint32_t a1 = *(const uint32_t*)&g_X2[(size_t)m1 * DIN + ka];
        uint32_t a2 = *(const uint32_t*)&g_X2[(size_t)m0 * DIN + ka + 8];
        uint32_t a3 = *(const uint32_t*)&g_X2[(size_t)m1 * DIN + ka + 8];
#pragma unroll
        for (int nc = 0; nc < 4; nc++) {
            int n = n_base + nc * 8 + gid;
            uint32_t b0 = *(const uint32_t*)&g_WxT[(size_t)n * DIN + ka];
            uint32_t b1 = *(const uint32_t*)&g_WxT[(size_t)n * DIN + ka + 8];
            mma16816(c[nc], a0, a1, a2, a3, b0, b1);
        }
    }

    // store to [t][b][col] layout
    const int b0i = m0 >> 9, s0 = m0 & 511;
    const int b1i = m1 >> 9, s1 = m1 & 511;
    const size_t row0 = (size_t)s0 * BATCH + b0i;
    const size_t row1 = (size_t)s1 * BATCH + b1i;
#pragma unroll
    for (int nc = 0; nc < 4; nc++) {
        int col = n_base + nc * 8 + tig * 2;
        float bx = g_bias[col], by = g_bias[col + 1];
        float2 v0 = make_float2(c[nc][0] + bx, c[nc][1] + by);
        float2 v1 = make_float2(c[nc][2] + bx, c[nc][3] + by);
        *(float2*)&g_xg[row0 * NG + col] = v0;
        *(float2*)&g_xg[row1 * NG + col] = v1;
    }
}

// ---------------- persistent scan kernel --------------------------------------
// grid: 128 blocks x 256 threads (8 warps). Block owns h-slice [h0, h0+8) x 4 gates.
// Wh slice (32 n-rows x 1024 k) in smem for the whole scan.
// H staged into smem each step via cp.async. 2-way K split across warp groups.
// C state in registers (warp group 0). Grid barrier between steps.
#define SW_STRIDE 1032   // padded row stride in halfs (conflict-free LDS)
#define RED_STRIDE 17    // padded partial-sum stride (floats)

#define SMEM_WH_HALFS   (32 * SW_STRIDE)                  // 33024 halfs
#define SMEM_H_HALFS    (64 * SW_STRIDE)                  // 66048 halfs
#define SCAN_SMEM_BYTES ((SMEM_WH_HALFS + SMEM_H_HALFS) * 2)   // 198144 B

__global__ void __launch_bounds__(256, 1) k_scan()
{
    extern __shared__ __half smem[];
    __half* sWh = smem;                         // [32][SW_STRIDE]
    __half* sH  = smem + SMEM_WH_HALFS;         // [64][SW_STRIDE]
    float*  sRed = (float*)sH;                  // reused after MMA reads complete

    const int tid   = threadIdx.x;
    const int warp  = tid >> 5;
    const int lane  = tid & 31;
    const int gid   = lane >> 2;
    const int tig   = lane & 3;
    const int kgrp  = warp >> 2;            // 0: k in [0,512), 1: [512,1024)
    const int wr    = warp & 3;             // row-group
    const int h0    = blockIdx.x * 8;
    const int r0    = wr * 16 + gid;        // batch row A
    const int r1    = r0 + 8;               // batch row B
    const int kbase = kgrp * 512;

    // ---- load Wh slice into smem (once) ----
    for (int i = tid; i < 32 * 128; i += 256) {
        int row = i >> 7;             // 0..31
        int c8  = (i & 127) * 8;      // half offset
        int g   = row >> 3, hh = row & 7;
        uint4 v = *(const uint4*)&g_WhT[((size_t)(g * HID + h0 + hh)) * HID + c8];
        *(uint4*)&sWh[row * SW_STRIDE + c8] = v;
    }

    // ---- C state in registers (warp group 0 only uses it) ----
    const int hc = h0 + tig * 2;
    float C00 = g_C[r0 * HID + hc];
    float C01 = g_C[r0 * HID + hc + 1];
    float C10 = g_C[r1 * HID + hc];
    float C11 = g_C[r1 * HID + hc + 1];
    __syncthreads();

    for (int t = 0; t < SEQ; t++) {
        const __half* __restrict__ Hin  = g_H2[t & 1];
        __half* __restrict__       Hout = g_H2[(t + 1) & 1];

        // ---- stage H (64 x 1024 halfs = 128KB) into smem via cp.async ----
        {
            const uint32_t sbase = smem_u32(sH);
#pragma unroll 8
            for (int i = tid; i < 8192; i += 256) {
                int row  = i >> 7;
                int col8 = (i & 127) * 8;
                cp_async16(sbase + (row * SW_STRIDE + col8) * 2,
                           &Hin[row * HID + col8]);
            }
            asm volatile("cp.async.commit_group;");
        }

        // ---- accumulators: group 0 starts from xg, group 1 from zero ----
        float c[4][4];
        if (kgrp == 0) {
            const size_t xr0 = ((size_t)t * BATCH + r0) * NG;
            const size_t xr1 = ((size_t)t * BATCH + r1) * NG;
#pragma unroll
            for (int g = 0; g < 4; g++) {
                int col = g * HID + hc;
                float2 x0 = ldcg_f2(&g_xg[xr0 + col]);
                float2 x1 = ldcg_f2(&g_xg[xr1 + col]);
                c[g][0] = x0.x; c[g][1] = x0.y; c[g][2] = x1.x; c[g][3] = x1.y;
            }
        } else {
#pragma unroll
            for (int g = 0; g < 4; g++)
#pragma unroll
                for (int r = 0; r < 4; r++) c[g][r] = 0.0f;
        }

        asm volatile("cp.async.wait_group 0;");
        __syncthreads();

        // ---- K loop over this warp group's half ----
#pragma unroll 4
        for (int ki = 0; ki < 512; ki += 16) {
            int ka = kbase + ki + tig * 2;
            uint32_t a0 = *(const uint32_t*)&sH[r0 * SW_STRIDE + ka];
            uint32_t a1 = *(const uint32_t*)&sH[r1 * SW_STRIDE + ka];
            uint32_t a2 = *(const uint32_t*)&sH[r0 * SW_STRIDE + ka + 8];
            uint32_t a3 = *(const uint32_t*)&sH[r1 * SW_STRIDE + ka + 8];
#pragma unroll
            for (int g = 0; g < 4; g++) {
                const __half* brow = &sWh[(g * 8 + gid) * SW_STRIDE + ka];
                uint32_t b0 = *(const uint32_t*)brow;
                uint32_t b1 = *(const uint32_t*)(brow + 8);
                mma16816(c[g], a0, a1, a2, a3, b0, b1);
            }
        }

        __syncthreads();   // all sH reads done; sRed may now alias sH

        // ---- split-K reduce: group 1 -> smem, group 0 adds ----
        if (kgrp == 1) {
            float* dst = &sRed[(wr * 32 + lane) * RED_STRIDE];
#pragma unroll
            for (int g = 0; g < 4; g++)
#pragma unroll
                for (int r = 0; r < 4; r++) dst[g * 4 + r] = c[g][r];
        }
        __syncthreads();

        if (kgrp == 0) {
            const float* src = &sRed[(wr * 32 + lane) * RED_STRIDE];
#pragma unroll
            for (int g = 0; g < 4; g++)
#pragma unroll
                for (int r = 0; r < 4; r++) c[g][r] += src[g * 4 + r];

            // ---- epilogue: gates, C/H update ----
#pragma unroll
            for (int p = 0; p < 2; p++) {
                int br = p ? r1 : r0;
                int ri = p * 2;
                float iv0 = sigf(c[0][ri]),  iv1 = sigf(c[0][ri + 1]);
                float fv0 = sigf(c[1][ri]),  fv1 = sigf(c[1][ri + 1]);
                float ov0 = sigf(c[2][ri]),  ov1 = sigf(c[2][ri + 1]);
                float cv0 = tanhf(c[3][ri]), cv1 = tanhf(c[3][ri + 1]);
                float Ca = p ? C10 : C00;
                float Cb = p ? C11 : C01;
                float Cn0 = fv0 * Ca + iv0 * cv0;
                float Cn1 = fv1 * Cb + iv1 * cv1;
                if (p) { C10 = Cn0; C11 = Cn1; } else { C00 = Cn0; C01 = Cn1; }
                float Hn0 = ov0 * tanhf(Cn0);
                float Hn1 = ov1 * tanhf(Cn1);
                __half2 hv = __floats2half2_rn(Hn0, Hn1);
                asm volatile("st.global.cg.b32 [%0], %1;" ::
                             "l"(&Hout[br * HID + hc]), "r"(*(uint32_t*)&hv));
                asm volatile("st.global.cg.v2.f32 [%0], {%1,%2};" ::
                             "l"(&g_Hs[((size_t)br * SEQ + t) * HID + hc]),
                             "f"(Hn0), "f"(Hn1));
            }
        }

        // ---- grid-wide barrier ----
        __threadfence();
        __syncthreads();
        if (tid == 0) {
            asm volatile("red.release.gpu.global.add.u32 [%0], 1;" :: "l"(&g_bar_count));
            unsigned target = 128u * (unsigned)(t + 1);
            unsigned v;
            do {
                asm volatile("ld.acquire.gpu.global.u32 %0, [%1];" : "=r"(v) : "l"(&g_bar_count));
            } while (v < target);
        }
        __syncthreads();
    }

    // write back C state (group 0 owns it)
    if (kgrp == 0) {
        g_C[r0 * HID + hc]     = C00;
        g_C[r0 * HID + hc + 1] = C01;
        g_C[r1 * HID + hc]     = C10;
        g_C[r1 * HID + hc + 1] = C11;
    }
}

// ---------------- pred = Hs @ Wd + bd ----------------------------------------
__global__ void k_pred(const float* __restrict__ Wd, const float* __restrict__ bd,
                       float* __restrict__ out, int out_size)
{
    int wg   = (blockIdx.x * blockDim.x + threadIdx.x) >> 5;   // one warp per row
    int lane = threadIdx.x & 31;
    if (wg >= MTOT) return;
    float s = 0.0f;
    const float* row = &g_Hs[(size_t)wg * HID];
#pragma unroll 8
    for (int k = lane; k < HID; k += 32) s += row[k] * Wd[k];
#pragma unroll
    for (int off = 16; off; off >>= 1) s += __shfl_down_sync(0xFFFFFFFFu, s, off);
    if (lane == 0 && wg < out_size) out[wg] = s + bd[0];
}

// ---------------- final Hf / Cf copy-out -------------------------------------
__global__ void k_final(float* __restrict__ out, int out_size)
{
    int i = blockIdx.x * blockDim.x + threadIdx.x;
    if (i >= BATCH * HID) return;
    int b = i >> 10, h = i & 1023;
    int o1 = MTOT + i;                  // Hf
    int o2 = MTOT + BATCH * HID + i;    // Cf
    if (o1 < out_size) out[o1] = g_Hs[(size_t)(b * SEQ + (SEQ - 1)) * HID + h];
    if (o2 < out_size) out[o2] = g_C[i];
}

// ---------------- launch ------------------------------------------------------
extern "C" void kernel_launch(void* const* d_in, const int* in_sizes, int n_in,
                              void* d_out, int out_size)
{
    const float* X   = (const float*)d_in[0];
    const float* H0  = (const float*)d_in[1];
    const float* C0  = (const float*)d_in[2];
    const float* Wxi = (const float*)d_in[3];
    const float* Whi = (const float*)d_in[4];
    const float* bi  = (const float*)d_in[5];
    const float* Wxf = (const float*)d_in[6];
    const float* Whf = (const float*)d_in[7];
    const float* bf  = (const float*)d_in[8];
    const float* Wxo = (const float*)d_in[9];
    const float* Who = (const float*)d_in[10];
    const float* bo  = (const float*)d_in[11];
    const float* Wxc = (const float*)d_in[12];
    const float* Whc = (const float*)d_in[13];
    const float* bc  = (const float*)d_in[14];
    const float* Wd  = (const float*)d_in[15];
    const float* bd  = (const float*)d_in[16];
    float* out = (float*)d_out;

    static int smem_set = 0;
    if (!smem_set) {
        cudaFuncSetAttribute(k_scan, cudaFuncAttributeMaxDynamicSharedMemorySize,
                             SCAN_SMEM_BYTES);
        smem_set = 1;
    }

    // prep
    k_init<<<1, 32>>>();
    k_convX<<<(MTOT * DIN + 1023) / 1024, 1024>>>(X);
    k_prepWxT<<<(NG * DIN + 255) / 256, 256>>>(Wxi, Wxf, Wxo, Wxc);
    k_prepWhT<<<(NG * HID + 255) / 256, 256>>>(Whi, Whf, Who, Whc);
    k_prepBias<<<(NG + 255) / 256, 256>>>(bi, bf, bo, bc);
    k_prepState<<<(BATCH * HID + 255) / 256, 256>>>(H0, C0);

    // phase 1: xg
    dim3 g1(NG / 32, MTOT / 64);
    k_xg<<<g1, 128>>>();

    // persistent scan (all 512 steps in one kernel)
    k_scan<<<128, 256, SCAN_SMEM_BYTES>>>();

    // outputs
    k_pred<<<(MTOT * 32 + 255) / 256, 256>>>(Wd, bd, out, out_size);
    k_final<<<(BATCH * HID + 255) / 256, 256>>>(out, out_size);
}

// round 7
// speedup vs baseline: 2.7604x; 1.0811x over previous
#include <cuda_runtime.h>
#include <cuda_fp16.h>
#include <stdint.h>

// Problem dims
#define BATCH 64
#define SEQ   512
#define DIN   256
#define HID   1024
#define NG    4096            // 4*HID
#define MTOT  32768           // BATCH*SEQ

// ---------------- scratch (device globals; no allocations allowed) ------------
__device__ __half g_X2[(size_t)MTOT * DIN];          // 16.8 MB  X in fp16
__device__ __half g_WxT[(size_t)NG * DIN];           //  2 MB    Wx^T  [n][k]
__device__ __half g_WhT[(size_t)NG * HID];           //  8.4 MB  Wh^T  [n][k]
__device__ float  g_bias[NG];
__device__ float  g_xg[(size_t)MTOT * NG];           // 537 MB   xg, layout [t][b][4H]
__device__ __half g_H2[2][BATCH * HID];              // ping-pong H (fp16)
__device__ float  g_C[BATCH * HID];                  // cell state (fp32)
__device__ float  g_Hs[(size_t)MTOT * HID];          // 134 MB   all H_t (fp32), [b*SEQ+t][h]
__device__ unsigned g_bar_count;                     // grid barrier counter

// ---------------- helpers -----------------------------------------------------
__device__ __forceinline__ void mma16816(float c[4],
    uint32_t a0, uint32_t a1, uint32_t a2, uint32_t a3,
    uint32_t b0, uint32_t b1)
{
    asm volatile(
        "mma.sync.aligned.m16n8k16.row.col.f32.f16.f16.f32 "
        "{%0,%1,%2,%3}, {%4,%5,%6,%7}, {%8,%9}, {%0,%1,%2,%3};\n"
        : "+f"(c[0]), "+f"(c[1]), "+f"(c[2]), "+f"(c[3])
        : "r"(a0), "r"(a1), "r"(a2), "r"(a3), "r"(b0), "r"(b1));
}

__device__ __forceinline__ float sigf(float x) { return 1.0f / (1.0f + __expf(-x)); }

__device__ __forceinline__ float2 ldcg_f2(const float* p) {
    float2 v;
    asm volatile("ld.global.cg.v2.f32 {%0,%1}, [%2];" : "=f"(v.x), "=f"(v.y) : "l"(p));
    return v;
}

__device__ __forceinline__ uint32_t smem_u32(const void* p) {
    uint32_t a;
    asm("{ .reg .u64 t; cvta.to.shared.u64 t, %1; cvt.u32.u64 %0, t; }" : "=r"(a) : "l"(p));
    return a;
}

// ---------------- prep kernels ------------------------------------------------
__global__ void k_init()
{
    if (threadIdx.x == 0 && blockIdx.x == 0) g_bar_count = 0u;
}

__global__ void k_convX(const float* __restrict__ X)
{
    size_t i = (size_t)blockIdx.x * blockDim.x + threadIdx.x;
    if (i < (size_t)MTOT * DIN) g_X2[i] = __float2half(X[i]);
}

__global__ void k_prepWxT(const float* __restrict__ Wxi, const float* __restrict__ Wxf,
                          const float* __restrict__ Wxo, const float* __restrict__ Wxc)
{
    int idx = blockIdx.x * blockDim.x + threadIdx.x;       // over NG*DIN
    if (idx >= NG * DIN) return;
    int n = idx >> 8;          // /256
    int k = idx & 255;
    int gate = n >> 10, h = n & 1023;
    const float* W = (gate == 0) ? Wxi : (gate == 1) ? Wxf : (gate == 2) ? Wxo : Wxc;
    g_WxT[idx] = __float2half(W[k * HID + h]);
}

__global__ void k_prepWhT(const float* __restrict__ Whi, const float* __restrict__ Whf,
                          const float* __restrict__ Who, const float* __restrict__ Whc)
{
    int idx = blockIdx.x * blockDim.x + threadIdx.x;       // over NG*HID
    if (idx >= NG * HID) return;
    int n = idx >> 10;         // /1024
    int k = idx & 1023;
    int gate = n >> 10, h = n & 1023;
    const float* W = (gate == 0) ? Whi : (gate == 1) ? Whf : (gate == 2) ? Who : Whc;
    g_WhT[idx] = __float2half(W[k * HID + h]);
}

__global__ void k_prepBias(const float* __restrict__ bi, const float* __restrict__ bf,
                           const float* __restrict__ bo, const float* __restrict__ bc)
{
    int n = blockIdx.x * blockDim.x + threadIdx.x;
    if (n >= NG) return;
    int gate = n >> 10, h = n & 1023;
    const float* b = (gate == 0) ? bi : (gate == 1) ? bf : (gate == 2) ? bo : bc;
    g_bias[n] = b[h];
}

__global__ void k_prepState(const float* __restrict__ H0, const float* __restrict__ C0)
{
    int i = blockIdx.x * blockDim.x + threadIdx.x;
    if (i >= BATCH * HID) return;
    g_H2[0][i] = __float2half(H0[i]);
    g_C[i] = C0[i];
}

// ---------------- phase 1: xg = X @ Wx + b  (fp16 MMA, fp32 acc) --------------
__global__ void __launch_bounds__(128) k_xg()
{
    const int warp = threadIdx.x >> 5;
    const int lane = threadIdx.x & 31;
    const int gid  = lane >> 2;
    const int tig  = lane & 3;
    const int m0   = blockIdx.y * 64 + warp * 16 + gid;
    const int m1   = m0 + 8;
    const int n_base = blockIdx.x * 32;

    float c[4][4];
#pragma unroll
    for (int nc = 0; nc < 4; nc++)
#pragma unroll
        for (int r = 0; r < 4; r++) c[nc][r] = 0.0f;

#pragma unroll 4
    for (int k0 = 0; k0 < DIN; k0 += 16) {
        int ka = k0 + tig * 2;
        uint32_t a0 = *(const uint32_t*)&g_X2[(size_t)m0 * DIN + ka];
        uint32_t a1 = *(const uint32_t*)&g_X2[(size_t)m1 * DIN + ka];
        uint32_t a2 = *(const uint32_t*)&g_X2[(size_t)m0 * DIN + ka + 8];
        uint32_t a3 = *(const uint32_t*)&g_X2[(size_t)m1 * DIN + ka + 8];
#pragma unroll
        for (int nc = 0; nc < 4; nc++) {
            int n = n_base + nc * 8 + gid;
            uint32_t b0 = *(const uint32_t*)&g_WxT[(size_t)n * DIN + ka];
            uint32_t b1 = *(const uint32_t*)&g_WxT[(size_t)n * DIN + ka + 8];
            mma16816(c[nc], a0, a1, a2, a3, b0, b1);
        }
    }

    const int b0i = m0 >> 9, s0 = m0 & 511;
    const int b1i = m1 >> 9, s1 = m1 & 511;
    const size_t row0 = (size_t)s0 * BATCH + b0i;
    const size_t row1 = (size_t)s1 * BATCH + b1i;
#pragma unroll
    for (int nc = 0; nc < 4; nc++) {
        int col = n_base + nc * 8 + tig * 2;
        float bx = g_bias[col], by = g_bias[col + 1];
        float2 v0 = make_float2(c[nc][0] + bx, c[nc][1] + by);
        float2 v1 = make_float2(c[nc][2] + bx, c[nc][3] + by);
        *(float2*)&g_xg[row0 * NG + col] = v0;
        *(float2*)&g_xg[row1 * NG + col] = v1;
    }
}

// ---------------- persistent scan kernel --------------------------------------
// grid: 128 blocks x 256 threads (8 warps). Block owns h-slice [h0, h0+8) x 4 gates.
// Wh slice in smem for whole scan. H staged per step via TMA bulk copy (64 row
// copies, 1 issuing thread) + mbarrier. 2-way K split. Grid barrier between steps.
#define SW_STRIDE 1032   // padded row stride in halfs (conflict-free LDS)
#define RED_STRIDE 17    // padded partial-sum stride (floats)

#define SMEM_WH_HALFS   (32 * SW_STRIDE)                  // 33024 halfs
#define SMEM_H_HALFS    (64 * SW_STRIDE)                  // 66048 halfs
#define SCAN_SMEM_BYTES ((SMEM_WH_HALFS + SMEM_H_HALFS) * 2)   // 198144 B
#define H_BYTES_TOTAL   (BATCH * HID * 2)                 // 131072 B per step

__global__ void __launch_bounds__(256, 1) k_scan()
{
    extern __shared__ __half smem[];
    __half* sWh = smem;                         // [32][SW_STRIDE]
    __half* sH  = smem + SMEM_WH_HALFS;         // [64][SW_STRIDE]
    float*  sRed = (float*)sH;                  // reused after MMA reads complete
    __shared__ __align__(8) uint64_t mbar;

    const int tid   = threadIdx.x;
    const int warp  = tid >> 5;
    const int lane  = tid & 31;
    const int gid   = lane >> 2;
    const int tig   = lane & 3;
    const int kgrp  = warp >> 2;            // 0: k in [0,512), 1: [512,1024)
    const int wr    = warp & 3;             // row-group
    const int h0    = blockIdx.x * 8;
    const int r0    = wr * 16 + gid;        // batch row A
    const int r1    = r0 + 8;               // batch row B
    const int kbase = kgrp * 512;

    const uint32_t mbar_a = smem_u32(&mbar);
    const uint32_t sH_a   = smem_u32(sH);

    if (tid == 0) {
        asm volatile("mbarrier.init.shared.b64 [%0], 1;" :: "r"(mbar_a));
    }

    // ---- load Wh slice into smem (once) ----
    for (int i = tid; i < 32 * 128; i += 256) {
        int row = i >> 7;             // 0..31
        int c8  = (i & 127) * 8;      // half offset
        int g   = row >> 3, hh = row & 7;
        uint4 v = *(const uint4*)&g_WhT[((size_t)(g * HID + h0 + hh)) * HID + c8];
        *(uint4*)&sWh[row * SW_STRIDE + c8] = v;
    }

    // ---- C state in registers (warp group 0 uses it) ----
    const int hc = h0 + tig * 2;
    float C00 = g_C[r0 * HID + hc];
    float C01 = g_C[r0 * HID + hc + 1];
    float C10 = g_C[r1 * HID + hc];
    float C11 = g_C[r1 * HID + hc + 1];
    __syncthreads();

    for (int t = 0; t < SEQ; t++) {
        const __half* __restrict__ Hin  = g_H2[t & 1];
        __half* __restrict__       Hout = g_H2[(t + 1) & 1];

        // ---- stage H (64 rows x 2048B) via TMA bulk copies; 1 issuing thread ----
        if (tid == 0) {
            asm volatile("fence.proxy.async.shared::cta;" ::: "memory");
            asm volatile("mbarrier.arrive.expect_tx.shared.b64 _, [%0], %1;"
                         :: "r"(mbar_a), "r"((uint32_t)H_BYTES_TOTAL));
#pragma unroll 8
            for (int row = 0; row < 64; row++) {
                asm volatile(
                    "cp.async.bulk.shared::cta.global.mbarrier::complete_tx::bytes "
                    "[%0], [%1], %2, [%3];"
                    :: "r"(sH_a + (uint32_t)(row * SW_STRIDE * 2)),
                       "l"(&Hin[row * HID]),
                       "r"((uint32_t)(HID * 2)),
                       "r"(mbar_a)
                    : "memory");
            }
        }

        // ---- accumulators: group 0 starts from xg, group 1 from zero ----
        float c[4][4];
        if (kgrp == 0) {
            const size_t xr0 = ((size_t)t * BATCH + r0) * NG;
            const size_t xr1 = ((size_t)t * BATCH + r1) * NG;
#pragma unroll
            for (int g = 0; g < 4; g++) {
                int col = g * HID + hc;
                float2 x0 = ldcg_f2(&g_xg[xr0 + col]);
                float2 x1 = ldcg_f2(&g_xg[xr1 + col]);
                c[g][0] = x0.x; c[g][1] = x0.y; c[g][2] = x1.x; c[g][3] = x1.y;
            }
        } else {
#pragma unroll
            for (int g = 0; g < 4; g++)
#pragma unroll
                for (int r = 0; r < 4; r++) c[g][r] = 0.0f;
        }

        // ---- wait for H tile ----
        {
            const uint32_t parity = (uint32_t)(t & 1);
            uint32_t done;
            asm volatile(
                "{\n\t.reg .pred p;\n\t"
                "mbarrier.try_wait.parity.acquire.cta.shared::cta.b64 p, [%1], %2;\n\t"
                "selp.b32 %0, 1, 0, p;\n\t}"
                : "=r"(done) : "r"(mbar_a), "r"(parity) : "memory");
            if (!done) {
                asm volatile(
                    "{\n\t.reg .pred P1;\n\t"
                    "W_%=:\n\t"
                    "mbarrier.try_wait.parity.acquire.cta.shared::cta.b64 P1, [%0], %1, 0x989680;\n\t"
                    "@P1 bra.uni D_%=;\n\t"
                    "bra.uni W_%=;\n\t"
                    "D_%=:\n\t}"
                    :: "r"(mbar_a), "r"(parity) : "memory");
            }
        }

        // ---- K loop over this warp group's half ----
#pragma unroll 4
        for (int ki = 0; ki < 512; ki += 16) {
            int ka = kbase + ki + tig * 2;
            uint32_t a0 = *(const uint32_t*)&sH[r0 * SW_STRIDE + ka];
            uint32_t a1 = *(const uint32_t*)&sH[r1 * SW_STRIDE + ka];
            uint32_t a2 = *(const uint32_t*)&sH[r0 * SW_STRIDE + ka + 8];
            uint32_t a3 = *(const uint32_t*)&sH[r1 * SW_STRIDE + ka + 8];
#pragma unroll
            for (int g = 0; g < 4; g++) {
                const __half* brow = &sWh[(g * 8 + gid) * SW_STRIDE + ka];
                uint32_t b0 = *(const uint32_t*)brow;
                uint32_t b1 = *(const uint32_t*)(brow + 8);
                mma16816(c[g], a0, a1, a2, a3, b0, b1);
            }
        }

        __syncthreads();   // all sH reads done; sRed may now alias sH

        // ---- split-K reduce: group 1 -> smem, group 0 adds ----
        if (kgrp == 1) {
            float* dst = &sRed[(wr * 32 + lane) * RED_STRIDE];
#pragma unroll
            for (int g = 0; g < 4; g++)
#pragma unroll
                for (int r = 0; r < 4; r++) dst[g * 4 + r] = c[g][r];
        }
        __syncthreads();

        if (kgrp == 0) {
            const float* src = &sRed[(wr * 32 + lane) * RED_STRIDE];
#pragma unroll
            for (int g = 0; g < 4; g++)
#pragma unroll
                for (int r = 0; r < 4; r++) c[g][r] += src[g * 4 + r];

            // ---- epilogue: gates, C/H update ----
#pragma unroll
            for (int p = 0; p < 2; p++) {
                int br = p ? r1 : r0;
                int ri = p * 2;
                float iv0 = sigf(c[0][ri]),  iv1 = sigf(c[0][ri + 1]);
                float fv0 = sigf(c[1][ri]),  fv1 = sigf(c[1][ri + 1]);
                float ov0 = sigf(c[2][ri]),  ov1 = sigf(c[2][ri + 1]);
                float cv0 = tanhf(c[3][ri]), cv1 = tanhf(c[3][ri + 1]);
                float Ca = p ? C10 : C00;
                float Cb = p ? C11 : C01;
                float Cn0 = fv0 * Ca + iv0 * cv0;
                float Cn1 = fv1 * Cb + iv1 * cv1;
                if (p) { C10 = Cn0; C11 = Cn1; } else { C00 = Cn0; C01 = Cn1; }
                float Hn0 = ov0 * tanhf(Cn0);
                float Hn1 = ov1 * tanhf(Cn1);
                __half2 hv = __floats2half2_rn(Hn0, Hn1);
                asm volatile("st.global.cg.b32 [%0], %1;" ::
                             "l"(&Hout[br * HID + hc]), "r"(*(uint32_t*)&hv));
                asm volatile("st.global.cg.v2.f32 [%0], {%1,%2};" ::
                             "l"(&g_Hs[((size_t)br * SEQ + t) * HID + hc]),
                             "f"(Hn0), "f"(Hn1));
            }
        }

        // ---- grid-wide barrier ----
        __threadfence();
        __syncthreads();
        if (tid == 0) {
            asm volatile("red.release.gpu.global.add.u32 [%0], 1;" :: "l"(&g_bar_count));
            unsigned target = 128u * (unsigned)(t + 1);
            unsigned v;
            do {
                asm volatile("ld.acquire.gpu.global.u32 %0, [%1];" : "=r"(v) : "l"(&g_bar_count));
            } while (v < target);
        }
        __syncthreads();
    }

    // write back C state (group 0 owns it)
    if (kgrp == 0) {
        g_C[r0 * HID + hc]     = C00;
        g_C[r0 * HID + hc + 1] = C01;
        g_C[r1 * HID + hc]     = C10;
        g_C[r1 * HID + hc + 1] = C11;
    }
}

// ---------------- pred = Hs @ Wd + bd ----------------------------------------
__global__ void k_pred(const float* __restrict__ Wd, const float* __restrict__ bd,
                       float* __restrict__ out, int out_size)
{
    int wg   = (blockIdx.x * blockDim.x + threadIdx.x) >> 5;   // one warp per row
    int lane = threadIdx.x & 31;
    if (wg >= MTOT) return;
    float s = 0.0f;
    const float* row = &g_Hs[(size_t)wg * HID];
#pragma unroll 8
    for (int k = lane; k < HID; k += 32) s += row[k] * Wd[k];
#pragma unroll
    for (int off = 16; off; off >>= 1) s += __shfl_down_sync(0xFFFFFFFFu, s, off);
    if (lane == 0 && wg < out_size) out[wg] = s + bd[0];
}

// ---------------- final Hf / Cf copy-out -------------------------------------
__global__ void k_final(float* __restrict__ out, int out_size)
{
    int i = blockIdx.x * blockDim.x + threadIdx.x;
    if (i >= BATCH * HID) return;
    int b = i >> 10, h = i & 1023;
    int o1 = MTOT + i;                  // Hf
    int o2 = MTOT + BATCH * HID + i;    // Cf
    if (o1 < out_size) out[o1] = g_Hs[(size_t)(b * SEQ + (SEQ - 1)) * HID + h];
    if (o2 < out_size) out[o2] = g_C[i];
}

// ---------------- launch ------------------------------------------------------
extern "C" void kernel_launch(void* const* d_in, const int* in_sizes, int n_in,
                              void* d_out, int out_size)
{
    const float* X   = (const float*)d_in[0];
    const float* H0  = (const float*)d_in[1];
    const float* C0  = (const float*)d_in[2];
    const float* Wxi = (const float*)d_in[3];
    const float* Whi = (const float*)d_in[4];
    const float* bi  = (const float*)d_in[5];
    const float* Wxf = (const float*)d_in[6];
    const float* Whf = (const float*)d_in[7];
    const float* bf  = (const float*)d_in[8];
    const float* Wxo = (const float*)d_in[9];
    const float* Who = (const float*)d_in[10];
    const float* bo  = (const float*)d_in[11];
    const float* Wxc = (const float*)d_in[12];
    const float* Whc = (const float*)d_in[13];
    const float* bc  = (const float*)d_in[14];
    const float* Wd  = (const float*)d_in[15];
    const float* bd  = (const float*)d_in[16];
    float* out = (float*)d_out;

    static int smem_set = 0;
    if (!smem_set) {
        cudaFuncSetAttribute(k_scan, cudaFuncAttributeMaxDynamicSharedMemorySize,
                             SCAN_SMEM_BYTES);
        smem_set = 1;
    }

    // prep
    k_init<<<1, 32>>>();
    k_convX<<<(MTOT * DIN + 1023) / 1024, 1024>>>(X);
    k_prepWxT<<<(NG * DIN + 255) / 256, 256>>>(Wxi, Wxf, Wxo, Wxc);
    k_prepWhT<<<(NG * HID + 255) / 256, 256>>>(Whi, Whf, Who, Whc);
    k_prepBias<<<(NG + 255) / 256, 256>>>(bi, bf, bo, bc);
    k_prepState<<<(BATCH * HID + 255) / 256, 256>>>(H0, C0);

    // phase 1: xg
    dim3 g1(NG / 32, MTOT / 64);
    k_xg<<<g1, 128>>>();

    // persistent scan (all 512 steps in one kernel)
    k_scan<<<128, 256, SCAN_SMEM_BYTES>>>();

    // outputs
    k_pred<<<(MTOT * 32 + 255) / 256, 256>>>(Wd, bd, out, out_size);
    k_final<<<(BATCH * HID + 255) / 256, 256>>>(out, out_size);
}